// round 2
// baseline (speedup 1.0000x reference)
#include <cuda_runtime.h>
#include <math.h>

// Problem dims (fixed by the dataset)
constexpr int T_ = 2048;
constexpr int S_ = 2048;
constexpr int B_ = 16;
constexpr int D_ = 1024;

// GEMM tiling
constexpr int BM = 128, BN = 128, BK = 16;
constexpr int LDT = BM + 4;  // padded smem stride (132 floats; row base stays 16B aligned)

// Scratch (allocation-free rule: __device__ globals)
__device__ float g_scores[(size_t)B_ * T_ * S_];   // 256 MB
__device__ float g_mix[(size_t)B_ * T_ * D_];      // 128 MB
__device__ float g_rowmax[B_ * T_];
__device__ float g_rowinv[B_ * T_];

// ---------------------------------------------------------------------------
// K1: scores[b,t,s] = sum_d q[t,b,d] * c[s,b,d]   (NT GEMM per batch)
// q layout [T,B,D], c layout [S,B,D]
// ---------------------------------------------------------------------------
__global__ __launch_bounds__(256) void k_scores(const float* __restrict__ q,
                                                const float* __restrict__ c) {
    __shared__ float As[BK][LDT];
    __shared__ float Bs[BK][LDT];
    const int b  = blockIdx.z;
    const int t0 = blockIdx.y * BM;
    const int s0 = blockIdx.x * BN;
    const int tid = threadIdx.x;
    const int arow = tid >> 2;          // 0..63 (plus +64 for second load)
    const int akc  = (tid & 3) << 2;    // 0,4,8,12
    const int tx = tid & 15, ty = tid >> 4;

    const float* Abase = q + (size_t)t0 * (B_ * D_) + (size_t)b * D_;
    const float* Bbase = c + (size_t)s0 * (B_ * D_) + (size_t)b * D_;

    float acc[8][8];
#pragma unroll
    for (int i = 0; i < 8; i++)
#pragma unroll
        for (int j = 0; j < 8; j++) acc[i][j] = 0.f;

    for (int k0 = 0; k0 < D_; k0 += BK) {
#pragma unroll
        for (int h = 0; h < 2; h++) {
            const int m = arow + h * 64;
            float4 va = *(const float4*)(Abase + (size_t)m * (B_ * D_) + k0 + akc);
            As[akc + 0][m] = va.x; As[akc + 1][m] = va.y;
            As[akc + 2][m] = va.z; As[akc + 3][m] = va.w;
            float4 vb = *(const float4*)(Bbase + (size_t)m * (B_ * D_) + k0 + akc);
            Bs[akc + 0][m] = vb.x; Bs[akc + 1][m] = vb.y;
            Bs[akc + 2][m] = vb.z; Bs[akc + 3][m] = vb.w;
        }
        __syncthreads();
#pragma unroll
        for (int kk = 0; kk < BK; kk++) {
            float ra[8], rb[8];
            float4 a0 = *(const float4*)&As[kk][ty * 8];
            float4 a1 = *(const float4*)&As[kk][ty * 8 + 4];
            float4 b0 = *(const float4*)&Bs[kk][tx * 8];
            float4 b1 = *(const float4*)&Bs[kk][tx * 8 + 4];
            ra[0]=a0.x; ra[1]=a0.y; ra[2]=a0.z; ra[3]=a0.w;
            ra[4]=a1.x; ra[5]=a1.y; ra[6]=a1.z; ra[7]=a1.w;
            rb[0]=b0.x; rb[1]=b0.y; rb[2]=b0.z; rb[3]=b0.w;
            rb[4]=b1.x; rb[5]=b1.y; rb[6]=b1.z; rb[7]=b1.w;
#pragma unroll
            for (int i = 0; i < 8; i++)
#pragma unroll
                for (int j = 0; j < 8; j++) acc[i][j] += ra[i] * rb[j];
        }
        __syncthreads();
    }

#pragma unroll
    for (int i = 0; i < 8; i++) {
        float* row = g_scores + ((size_t)b * T_ + t0 + ty * 8 + i) * S_ + s0 + tx * 8;
        *(float4*)(row)     = make_float4(acc[i][0], acc[i][1], acc[i][2], acc[i][3]);
        *(float4*)(row + 4) = make_float4(acc[i][4], acc[i][5], acc[i][6], acc[i][7]);
    }
}

// ---------------------------------------------------------------------------
// K2: per-row online softmax stats over S, with the ==0 mask.
// One warp per row; 8 rows per CTA.
// ---------------------------------------------------------------------------
__global__ __launch_bounds__(256) void k_stats() {
    const int row  = blockIdx.x * 8 + (threadIdx.x >> 5);
    const int lane = threadIdx.x & 31;
    const float* p = g_scores + (size_t)row * S_;

    float m = -INFINITY, sum = 0.f;
    for (int s = lane * 4; s < S_; s += 128) {
        float4 v = *(const float4*)(p + s);
        float vals[4] = {v.x, v.y, v.z, v.w};
#pragma unroll
        for (int i = 0; i < 4; i++) {
            float val = vals[i];
            if (val != 0.0f) {
                if (val > m) { sum = sum * __expf(m - val) + 1.0f; m = val; }
                else         { sum += __expf(val - m); }
            }
        }
    }
#pragma unroll
    for (int off = 16; off; off >>= 1) {
        float mo = __shfl_xor_sync(0xffffffffu, m, off);
        float so = __shfl_xor_sync(0xffffffffu, sum, off);
        float mn = fmaxf(m, mo);
        sum = sum * __expf(m - mn) + so * __expf(mo - mn);
        m = mn;
    }
    if (lane == 0) {
        g_rowmax[row] = m;
        g_rowinv[row] = 1.0f / sum;
    }
}

// ---------------------------------------------------------------------------
// K3: mix[b,t,d] = sum_s P[b,t,s] * c[s,b,d]   (NN GEMM per batch)
// P computed on-the-fly from raw scores + (rowmax, rowinv).
// ---------------------------------------------------------------------------
__global__ __launch_bounds__(256) void k_mix(const float* __restrict__ c) {
    __shared__ float As[BK][LDT];
    __shared__ float Bs[BK][LDT];
    __shared__ float sMax[BM], sInv[BM];
    const int b  = blockIdx.z;
    const int t0 = blockIdx.y * BM;
    const int d0 = blockIdx.x * BN;
    const int tid = threadIdx.x;
    const int tx = tid & 15, ty = tid >> 4;
    const int arow = tid >> 2;
    const int akc  = (tid & 3) << 2;
    const int brow = tid >> 5;          // 0..7 (plus +8)
    const int bcol = (tid & 31) << 2;   // 0..124

    if (tid < BM) {
        int r = b * T_ + t0 + tid;
        sMax[tid] = g_rowmax[r];
        sInv[tid] = g_rowinv[r];
    }
    __syncthreads();

    const float* Abase = g_scores + ((size_t)b * T_ + t0) * S_;

    float acc[8][8];
#pragma unroll
    for (int i = 0; i < 8; i++)
#pragma unroll
        for (int j = 0; j < 8; j++) acc[i][j] = 0.f;

    for (int k0 = 0; k0 < S_; k0 += BK) {
#pragma unroll
        for (int h = 0; h < 2; h++) {
            const int m = arow + h * 64;
            float4 v = *(const float4*)(Abase + (size_t)m * S_ + k0 + akc);
            const float mx = sMax[m], iv = sInv[m];
            As[akc + 0][m] = (v.x == 0.f) ? 0.f : __expf(v.x - mx) * iv;
            As[akc + 1][m] = (v.y == 0.f) ? 0.f : __expf(v.y - mx) * iv;
            As[akc + 2][m] = (v.z == 0.f) ? 0.f : __expf(v.z - mx) * iv;
            As[akc + 3][m] = (v.w == 0.f) ? 0.f : __expf(v.w - mx) * iv;
        }
#pragma unroll
        for (int h = 0; h < 2; h++) {
            const int kk = brow + h * 8;
            float4 w = *(const float4*)(c + (size_t)(k0 + kk) * (B_ * D_) + (size_t)b * D_ + d0 + bcol);
            *(float4*)&Bs[kk][bcol] = w;
        }
        __syncthreads();
#pragma unroll
        for (int kk = 0; kk < BK; kk++) {
            float ra[8], rb[8];
            float4 a0 = *(const float4*)&As[kk][ty * 8];
            float4 a1 = *(const float4*)&As[kk][ty * 8 + 4];
            float4 b0 = *(const float4*)&Bs[kk][tx * 8];
            float4 b1 = *(const float4*)&Bs[kk][tx * 8 + 4];
            ra[0]=a0.x; ra[1]=a0.y; ra[2]=a0.z; ra[3]=a0.w;
            ra[4]=a1.x; ra[5]=a1.y; ra[6]=a1.z; ra[7]=a1.w;
            rb[0]=b0.x; rb[1]=b0.y; rb[2]=b0.z; rb[3]=b0.w;
            rb[4]=b1.x; rb[5]=b1.y; rb[6]=b1.z; rb[7]=b1.w;
#pragma unroll
            for (int i = 0; i < 8; i++)
#pragma unroll
                for (int j = 0; j < 8; j++) acc[i][j] += ra[i] * rb[j];
        }
        __syncthreads();
    }

#pragma unroll
    for (int i = 0; i < 8; i++) {
        float* row = g_mix + ((size_t)b * T_ + t0 + ty * 8 + i) * D_ + d0 + tx * 8;
        *(float4*)(row)     = make_float4(acc[i][0], acc[i][1], acc[i][2], acc[i][3]);
        *(float4*)(row + 4) = make_float4(acc[i][4], acc[i][5], acc[i][6], acc[i][7]);
    }
}

// ---------------------------------------------------------------------------
// K4: out[r, d] = tanh( sum_k combined[r,k] * W[d,k] + bias[d] )
// combined[r, k] = (k < D) ? mix[r, k] : q[t, b, k-D]  with r = b*T + t
// NT GEMM, M = B*T, N = D, K = 2D; fused bias + tanh epilogue.
// ---------------------------------------------------------------------------
__global__ __launch_bounds__(256) void k_out(const float* __restrict__ q,
                                             const float* __restrict__ W,
                                             const float* __restrict__ bias,
                                             float* __restrict__ out) {
    __shared__ float As[BK][LDT];
    __shared__ float Bs[BK][LDT];
    const int r0 = blockIdx.y * BM;   // global row (b*T + t); 128-block never crosses b
    const int d0 = blockIdx.x * BN;
    const int bidx = r0 / T_;
    const int t0   = r0 % T_;
    const int tid = threadIdx.x;
    const int tx = tid & 15, ty = tid >> 4;
    const int arow = tid >> 2;
    const int akc  = (tid & 3) << 2;

    float acc[8][8];
#pragma unroll
    for (int i = 0; i < 8; i++)
#pragma unroll
        for (int j = 0; j < 8; j++) acc[i][j] = 0.f;

    for (int k0 = 0; k0 < 2 * D_; k0 += BK) {
        const bool fromMix = (k0 < D_);
#pragma unroll
        for (int h = 0; h < 2; h++) {
            const int m = arow + h * 64;
            const float* src = fromMix
                ? (g_mix + (size_t)(r0 + m) * D_ + k0 + akc)
                : (q + (size_t)(t0 + m) * (B_ * D_) + (size_t)bidx * D_ + (k0 - D_) + akc);
            float4 va = *(const float4*)src;
            As[akc + 0][m] = va.x; As[akc + 1][m] = va.y;
            As[akc + 2][m] = va.z; As[akc + 3][m] = va.w;
            float4 vw = *(const float4*)(W + (size_t)(d0 + m) * (2 * D_) + k0 + akc);
            Bs[akc + 0][m] = vw.x; Bs[akc + 1][m] = vw.y;
            Bs[akc + 2][m] = vw.z; Bs[akc + 3][m] = vw.w;
        }
        __syncthreads();
#pragma unroll
        for (int kk = 0; kk < BK; kk++) {
            float ra[8], rb[8];
            float4 a0 = *(const float4*)&As[kk][ty * 8];
            float4 a1 = *(const float4*)&As[kk][ty * 8 + 4];
            float4 b0 = *(const float4*)&Bs[kk][tx * 8];
            float4 b1 = *(const float4*)&Bs[kk][tx * 8 + 4];
            ra[0]=a0.x; ra[1]=a0.y; ra[2]=a0.z; ra[3]=a0.w;
            ra[4]=a1.x; ra[5]=a1.y; ra[6]=a1.z; ra[7]=a1.w;
            rb[0]=b0.x; rb[1]=b0.y; rb[2]=b0.z; rb[3]=b0.w;
            rb[4]=b1.x; rb[5]=b1.y; rb[6]=b1.z; rb[7]=b1.w;
#pragma unroll
            for (int i = 0; i < 8; i++)
#pragma unroll
                for (int j = 0; j < 8; j++) acc[i][j] += ra[i] * rb[j];
        }
        __syncthreads();
    }

    float bs[8];
#pragma unroll
    for (int j = 0; j < 8; j++) bs[j] = __ldg(bias + d0 + tx * 8 + j);

#pragma unroll
    for (int i = 0; i < 8; i++) {
        float* row = out + (size_t)(r0 + ty * 8 + i) * D_ + d0 + tx * 8;
        float v[8];
#pragma unroll
        for (int j = 0; j < 8; j++) v[j] = tanhf(acc[i][j] + bs[j]);
        *(float4*)(row)     = make_float4(v[0], v[1], v[2], v[3]);
        *(float4*)(row + 4) = make_float4(v[4], v[5], v[6], v[7]);
    }
}

// ---------------------------------------------------------------------------
extern "C" void kernel_launch(void* const* d_in, const int* in_sizes, int n_in,
                              void* d_out, int out_size) {
    const float* out_t = (const float*)d_in[0];  // [T,B,D]
    const float* ctx   = (const float*)d_in[1];  // [S,B,D]
    const float* W     = (const float*)d_in[2];  // [D,2D]
    const float* bias  = (const float*)d_in[3];  // [D]
    float* out = (float*)d_out;                  // [B,T,D]

    dim3 g1(S_ / BN, T_ / BM, B_);
    k_scores<<<g1, 256>>>(out_t, ctx);

    k_stats<<<(B_ * T_) / 8, 256>>>();

    dim3 g3(D_ / BN, T_ / BM, B_);
    k_mix<<<g3, 256>>>(ctx);

    dim3 g4(D_ / BN, (B_ * T_) / BM);
    k_out<<<g4, 256>>>(out_t, W, bias, out);
}

// round 10
// speedup vs baseline: 1.7183x; 1.7183x over previous
#include <cuda_runtime.h>
#include <cuda_fp16.h>
#include <cstdint>
#include <math.h>

// ---------------------------------------------------------------- problem dims
constexpr int T_ = 2048, S_ = 2048, B_ = 16, D_ = 1024;
constexpr int K2_ = 2 * D_;

// ---------------------------------------------------------------- tiling
constexpr int BM = 128, BN = 128, BK = 32;
constexpr int ROWH = 40;               // halves per smem row (pad: 32 data + 8)
constexpr int RB = ROWH * 2;           // 80 bytes per row
constexpr int REG = BM * RB;           // 10240 B per operand region
constexpr int OFF_AH = 0, OFF_AL = REG, OFF_BH = 2 * REG, OFF_BL = 3 * REG;
constexpr int SM_BYTES = 4 * REG;      // 40960 B (static shared, no opt-in needed)

constexpr float PSCALE = 4096.0f;      // keep softmax-P "lo" split out of fp16 denormals
constexpr float INVP = 1.0f / 4096.0f;

// ---------------------------------------------------------------- scratch (__device__ globals)
__device__ float g_scores[(size_t)B_ * T_ * S_];        // 256 MB
__device__ float g_rowmax[B_ * T_];
__device__ float g_rowinv[B_ * T_];
__device__ __half g_q_hi[(size_t)B_ * T_ * D_];         // [B][T][D]
__device__ __half g_q_lo[(size_t)B_ * T_ * D_];
__device__ __half g_c_hi[(size_t)B_ * S_ * D_];         // [B][S][D]
__device__ __half g_c_lo[(size_t)B_ * S_ * D_];
__device__ __half g_cT_hi[(size_t)B_ * D_ * S_];        // [B][D][S]
__device__ __half g_cT_lo[(size_t)B_ * D_ * S_];
__device__ __half g_mix_hi[(size_t)B_ * T_ * D_];       // [B][T][D]
__device__ __half g_mix_lo[(size_t)B_ * T_ * D_];
__device__ __half g_W_hi[(size_t)D_ * K2_];             // [D][2D]
__device__ __half g_W_lo[(size_t)D_ * K2_];

// ---------------------------------------------------------------- helpers
__device__ __forceinline__ void mma4(float* c, const uint32_t* a, const uint32_t* b) {
    asm volatile("mma.sync.aligned.m16n8k16.row.col.f32.f16.f16.f32 "
                 "{%0,%1,%2,%3}, {%4,%5,%6,%7}, {%8,%9}, {%0,%1,%2,%3};"
                 : "+f"(c[0]), "+f"(c[1]), "+f"(c[2]), "+f"(c[3])
                 : "r"(a[0]), "r"(a[1]), "r"(a[2]), "r"(a[3]), "r"(b[0]), "r"(b[1]));
}
__device__ __forceinline__ void split2(float x, unsigned short& h, unsigned short& l) {
    __half hb = __float2half_rn(x);
    __half lb = __float2half_rn(x - __half2float(hb));
    h = __half_as_ushort(hb);
    l = __half_as_ushort(lb);
}

// Prefetch one 128x32-half region: 512 chunks of 16B, 2 per thread.
__device__ __forceinline__ void pref_region(uint4 (&r)[2], const __half* __restrict__ src,
                                            int ldk, int tid) {
#pragma unroll
    for (int j = 0; j < 2; j++) {
        int id = tid + j * 256;
        int row = id >> 2, c = id & 3;
        r[j] = *(const uint4*)(src + (size_t)row * ldk + c * 8);
    }
}
__device__ __forceinline__ void store_region(char* dst, const uint4 (&r)[2], int tid) {
#pragma unroll
    for (int j = 0; j < 2; j++) {
        int id = tid + j * 256;
        int row = id >> 2, c = id & 3;
        *(uint4*)(dst + row * RB + c * 16) = r[j];
    }
}

// Warp compute over one BK=32 tile: acc += Ah*Bh + Ah*Bl + Al*Bh.
// Fragments loaded with direct LDS per the PTX m16n8k16 fragment tables.
__device__ __forceinline__ void warp_mma(float (&acc)[4][4][4], const char* sm,
                                         int wm, int wn, int lane) {
    const int g = lane >> 2, tg = lane & 3;
#pragma unroll
    for (int ks = 0; ks < 2; ks++) {
        uint32_t ah[4][4], al[4][4];
#pragma unroll
        for (int mt = 0; mt < 4; mt++) {
            const int base = (wm * 64 + mt * 16 + g) * RB + (ks * 8 + tg) * 4;
            ah[mt][0] = *(const uint32_t*)(sm + OFF_AH + base);
            ah[mt][1] = *(const uint32_t*)(sm + OFF_AH + base + 8 * RB);
            ah[mt][2] = *(const uint32_t*)(sm + OFF_AH + base + 16);
            ah[mt][3] = *(const uint32_t*)(sm + OFF_AH + base + 8 * RB + 16);
            al[mt][0] = *(const uint32_t*)(sm + OFF_AL + base);
            al[mt][1] = *(const uint32_t*)(sm + OFF_AL + base + 8 * RB);
            al[mt][2] = *(const uint32_t*)(sm + OFF_AL + base + 16);
            al[mt][3] = *(const uint32_t*)(sm + OFF_AL + base + 8 * RB + 16);
        }
        uint32_t bh[4][2], bl[4][2];
#pragma unroll
        for (int nt = 0; nt < 4; nt++) {
            const int base = (wn * 32 + nt * 8 + g) * RB + (ks * 8 + tg) * 4;
            bh[nt][0] = *(const uint32_t*)(sm + OFF_BH + base);
            bh[nt][1] = *(const uint32_t*)(sm + OFF_BH + base + 16);
            bl[nt][0] = *(const uint32_t*)(sm + OFF_BL + base);
            bl[nt][1] = *(const uint32_t*)(sm + OFF_BL + base + 16);
        }
#pragma unroll
        for (int mt = 0; mt < 4; mt++)
#pragma unroll
            for (int nt = 0; nt < 4; nt++) {
                mma4(acc[mt][nt], ah[mt], bh[nt]);
                mma4(acc[mt][nt], ah[mt], bl[nt]);
                mma4(acc[mt][nt], al[mt], bh[nt]);
            }
    }
}

// ---------------------------------------------------------------- conversion kernels
// which == 0 -> write g_q_hi/lo, which == 1 -> write g_c_hi/lo.
// NOTE: the destination __device__ arrays are referenced from DEVICE code here;
// passing them as host-side kernel args was the R8/R9 bug (host shadow address).
__global__ __launch_bounds__(256) void k_split_qc(const float* __restrict__ src, int which) {
    __half* __restrict__ hi = which ? g_c_hi : g_q_hi;
    __half* __restrict__ lo = which ? g_c_lo : g_q_lo;
    size_t e = ((size_t)blockIdx.x * 256 + threadIdx.x) * 4;
    int t = (int)(e / (B_ * D_));
    int rem = (int)(e % (B_ * D_));
    int b = rem / D_, d = rem % D_;
    float4 v = *(const float4*)(src + e);
    unsigned short h[4], l[4];
    split2(v.x, h[0], l[0]); split2(v.y, h[1], l[1]);
    split2(v.z, h[2], l[2]); split2(v.w, h[3], l[3]);
    size_t o = ((size_t)b * T_ + t) * D_ + d;
    *(uint2*)(hi + o) = make_uint2((uint32_t)h[0] | ((uint32_t)h[1] << 16),
                                   (uint32_t)h[2] | ((uint32_t)h[3] << 16));
    *(uint2*)(lo + o) = make_uint2((uint32_t)l[0] | ((uint32_t)l[1] << 16),
                                   (uint32_t)l[2] | ((uint32_t)l[3] << 16));
}

__global__ __launch_bounds__(256) void k_split_cT(const float* __restrict__ c) {
    __shared__ float tile[32][33];
    int b = blockIdx.z, d0 = blockIdx.y * 32, s0 = blockIdx.x * 32;
    int tx = threadIdx.x, ty = threadIdx.y;
    for (int r = ty; r < 32; r += 8)
        tile[r][tx] = c[((size_t)(s0 + r) * B_ + b) * D_ + d0 + tx];
    __syncthreads();
    for (int r = ty; r < 32; r += 8) {
        unsigned short h, l;
        split2(tile[tx][r], h, l);
        size_t o = ((size_t)b * D_ + d0 + r) * S_ + s0 + tx;
        g_cT_hi[o] = __ushort_as_half(h);
        g_cT_lo[o] = __ushort_as_half(l);
    }
}

__global__ __launch_bounds__(256) void k_split_W(const float* __restrict__ W) {
    size_t e = ((size_t)blockIdx.x * 256 + threadIdx.x) * 4;
    float4 v = *(const float4*)(W + e);
    unsigned short h[4], l[4];
    split2(v.x, h[0], l[0]); split2(v.y, h[1], l[1]);
    split2(v.z, h[2], l[2]); split2(v.w, h[3], l[3]);
    *(uint2*)(g_W_hi + e) = make_uint2((uint32_t)h[0] | ((uint32_t)h[1] << 16),
                                       (uint32_t)h[2] | ((uint32_t)h[3] << 16));
    *(uint2*)(g_W_lo + e) = make_uint2((uint32_t)l[0] | ((uint32_t)l[1] << 16),
                                       (uint32_t)l[2] | ((uint32_t)l[3] << 16));
}

// ---------------------------------------------------------------- G1: scores = q @ c^T
__global__ __launch_bounds__(256) void g1_scores() {
    __shared__ __align__(16) char sm[SM_BYTES];
    const int tid = threadIdx.x, lane = tid & 31, wid = tid >> 5;
    const int wm = wid >> 2, wn = wid & 3;
    const int b = blockIdx.z, t0 = blockIdx.y * BM, s0 = blockIdx.x * BN;

    const __half* Ah = g_q_hi + ((size_t)b * T_ + t0) * D_;
    const __half* Al = g_q_lo + ((size_t)b * T_ + t0) * D_;
    const __half* Bh = g_c_hi + ((size_t)b * S_ + s0) * D_;
    const __half* Bl = g_c_lo + ((size_t)b * S_ + s0) * D_;

    float acc[4][4][4];
#pragma unroll
    for (int i = 0; i < 4; i++)
#pragma unroll
        for (int j = 0; j < 4; j++)
#pragma unroll
            for (int k = 0; k < 4; k++) acc[i][j][k] = 0.f;

    uint4 rah[2], ral[2], rbh[2], rbl[2];
    const int NI = D_ / BK;  // 32
    pref_region(rah, Ah, D_, tid);
    pref_region(ral, Al, D_, tid);
    pref_region(rbh, Bh, D_, tid);
    pref_region(rbl, Bl, D_, tid);
    for (int i = 0; i < NI; i++) {
        store_region(sm + OFF_AH, rah, tid);
        store_region(sm + OFF_AL, ral, tid);
        store_region(sm + OFF_BH, rbh, tid);
        store_region(sm + OFF_BL, rbl, tid);
        __syncthreads();
        if (i + 1 < NI) {
            int k0 = (i + 1) * BK;
            pref_region(rah, Ah + k0, D_, tid);
            pref_region(ral, Al + k0, D_, tid);
            pref_region(rbh, Bh + k0, D_, tid);
            pref_region(rbl, Bl + k0, D_, tid);
        }
        warp_mma(acc, sm, wm, wn, lane);
        __syncthreads();
    }

    const int g = lane >> 2, tg = lane & 3;
#pragma unroll
    for (int mt = 0; mt < 4; mt++)
#pragma unroll
        for (int nt = 0; nt < 4; nt++) {
            int r = t0 + wm * 64 + mt * 16 + g;
            int cix = s0 + wn * 32 + nt * 8 + tg * 2;
            float* p0 = g_scores + ((size_t)b * T_ + r) * S_ + cix;
            *(float2*)p0 = make_float2(acc[mt][nt][0], acc[mt][nt][1]);
            float* p1 = g_scores + ((size_t)b * T_ + r + 8) * S_ + cix;
            *(float2*)p1 = make_float2(acc[mt][nt][2], acc[mt][nt][3]);
        }
}

// ---------------------------------------------------------------- K2: softmax row stats (==0 mask)
__global__ __launch_bounds__(256) void k_stats() {
    const int row = blockIdx.x * 8 + (threadIdx.x >> 5);
    const int lane = threadIdx.x & 31;
    const float* p = g_scores + (size_t)row * S_;
    float m = -INFINITY, sum = 0.f;
    for (int s = lane * 4; s < S_; s += 128) {
        float4 v = *(const float4*)(p + s);
        float vals[4] = {v.x, v.y, v.z, v.w};
#pragma unroll
        for (int i = 0; i < 4; i++) {
            float val = vals[i];
            if (val != 0.0f) {
                if (val > m) { sum = sum * __expf(m - val) + 1.0f; m = val; }
                else         { sum += __expf(val - m); }
            }
        }
    }
#pragma unroll
    for (int off = 16; off; off >>= 1) {
        float mo = __shfl_xor_sync(0xffffffffu, m, off);
        float so = __shfl_xor_sync(0xffffffffu, sum, off);
        float mn = fmaxf(m, mo);
        sum = sum * __expf(m - mn) + so * __expf(mo - mn);
        m = mn;
    }
    if (lane == 0) { g_rowmax[row] = m; g_rowinv[row] = 1.0f / sum; }
}

// ---------------------------------------------------------------- G2: mix = softmax(scores) @ c
__global__ __launch_bounds__(256) void g2_mix() {
    __shared__ __align__(16) char sm[SM_BYTES];
    __shared__ float sMax[BM], sInv[BM];
    const int tid = threadIdx.x, lane = tid & 31, wid = tid >> 5;
    const int wm = wid >> 2, wn = wid & 3;
    const int b = blockIdx.z, t0 = blockIdx.y * BM, d0 = blockIdx.x * BN;

    if (tid < BM) {
        int r = b * T_ + t0 + tid;
        sMax[tid] = g_rowmax[r];
        sInv[tid] = g_rowinv[r];
    }
    __syncthreads();

    const float* Sc = g_scores + ((size_t)b * T_ + t0) * S_;
    const __half* Bh = g_cT_hi + ((size_t)b * D_ + d0) * S_;
    const __half* Bl = g_cT_lo + ((size_t)b * D_ + d0) * S_;

    float acc[4][4][4];
#pragma unroll
    for (int i = 0; i < 4; i++)
#pragma unroll
        for (int j = 0; j < 4; j++)
#pragma unroll
            for (int k = 0; k < 4; k++) acc[i][j][k] = 0.f;

    uint4 ras[4], rbh[2], rbl[2];   // ras: raw fp32 scores, 16 floats
    const int NI = S_ / BK;  // 64
    auto prefA = [&](int k0) {
#pragma unroll
        for (int j = 0; j < 4; j++) {
            int id = tid + j * 256;
            int row = id >> 3, c = id & 7;
            ras[j] = *(const uint4*)(Sc + (size_t)row * S_ + k0 + c * 4);
        }
    };
    prefA(0);
    pref_region(rbh, Bh, S_, tid);
    pref_region(rbl, Bl, S_, tid);
    for (int i = 0; i < NI; i++) {
        // store A with softmax conversion + hi/lo split (scaled by PSCALE)
#pragma unroll
        for (int j = 0; j < 4; j++) {
            int id = tid + j * 256;
            int row = id >> 3, c = id & 7;
            const float* xf = (const float*)&ras[j];
            float mx = sMax[row], iv = sInv[row];
            unsigned short h[4], l[4];
#pragma unroll
            for (int q = 0; q < 4; q++) {
                float x = xf[q];
                float pv = (x == 0.0f) ? 0.0f : __expf(x - mx) * iv * PSCALE;
                split2(pv, h[q], l[q]);
            }
            *(uint2*)(sm + OFF_AH + row * RB + c * 8) =
                make_uint2((uint32_t)h[0] | ((uint32_t)h[1] << 16),
                           (uint32_t)h[2] | ((uint32_t)h[3] << 16));
            *(uint2*)(sm + OFF_AL + row * RB + c * 8) =
                make_uint2((uint32_t)l[0] | ((uint32_t)l[1] << 16),
                           (uint32_t)l[2] | ((uint32_t)l[3] << 16));
        }
        store_region(sm + OFF_BH, rbh, tid);
        store_region(sm + OFF_BL, rbl, tid);
        __syncthreads();
        if (i + 1 < NI) {
            int k0 = (i + 1) * BK;
            prefA(k0);
            pref_region(rbh, Bh + k0, S_, tid);
            pref_region(rbl, Bl + k0, S_, tid);
        }
        warp_mma(acc, sm, wm, wn, lane);
        __syncthreads();
    }

    const int g = lane >> 2, tg = lane & 3;
#pragma unroll
    for (int mt = 0; mt < 4; mt++)
#pragma unroll
        for (int nt = 0; nt < 4; nt++) {
            int r = t0 + wm * 64 + mt * 16 + g;
            int cix = d0 + wn * 32 + nt * 8 + tg * 2;
#pragma unroll
            for (int hrow = 0; hrow < 2; hrow++) {
                size_t o = ((size_t)b * T_ + r + hrow * 8) * D_ + cix;
                unsigned short h0, l0, h1, l1;
                split2(acc[mt][nt][2 * hrow] * INVP,     h0, l0);
                split2(acc[mt][nt][2 * hrow + 1] * INVP, h1, l1);
                *(uint32_t*)(g_mix_hi + o) = (uint32_t)h0 | ((uint32_t)h1 << 16);
                *(uint32_t*)(g_mix_lo + o) = (uint32_t)l0 | ((uint32_t)l1 << 16);
            }
        }
}

// ---------------------------------------------------------------- G3: out = tanh([mix,q] @ W^T + b)
__global__ __launch_bounds__(256) void g3_out(const float* __restrict__ bias,
                                              float* __restrict__ out) {
    __shared__ __align__(16) char sm[SM_BYTES];
    __shared__ float sBias[BN];
    const int tid = threadIdx.x, lane = tid & 31, wid = tid >> 5;
    const int wm = wid >> 2, wn = wid & 3;
    const int r0 = blockIdx.y * BM, d0 = blockIdx.x * BN;
    if (tid < BN) sBias[tid] = bias[d0 + tid];
    __syncthreads();

    const __half* Wh = g_W_hi + (size_t)d0 * K2_;
    const __half* Wl = g_W_lo + (size_t)d0 * K2_;

    float acc[4][4][4];
#pragma unroll
    for (int i = 0; i < 4; i++)
#pragma unroll
        for (int j = 0; j < 4; j++)
#pragma unroll
            for (int k = 0; k < 4; k++) acc[i][j][k] = 0.f;

    uint4 rah[2], ral[2], rbh[2], rbl[2];
    const int NI = K2_ / BK;  // 64
    auto prefA = [&](int k0) {
        const __half* Ah = (k0 < D_) ? g_mix_hi + (size_t)r0 * D_ + k0
                                     : g_q_hi  + (size_t)r0 * D_ + (k0 - D_);
        const __half* Al = (k0 < D_) ? g_mix_lo + (size_t)r0 * D_ + k0
                                     : g_q_lo  + (size_t)r0 * D_ + (k0 - D_);
        pref_region(rah, Ah, D_, tid);
        pref_region(ral, Al, D_, tid);
    };
    prefA(0);
    pref_region(rbh, Wh, K2_, tid);
    pref_region(rbl, Wl, K2_, tid);
    for (int i = 0; i < NI; i++) {
        store_region(sm + OFF_AH, rah, tid);
        store_region(sm + OFF_AL, ral, tid);
        store_region(sm + OFF_BH, rbh, tid);
        store_region(sm + OFF_BL, rbl, tid);
        __syncthreads();
        if (i + 1 < NI) {
            int k0 = (i + 1) * BK;
            prefA(k0);
            pref_region(rbh, Wh + k0, K2_, tid);
            pref_region(rbl, Wl + k0, K2_, tid);
        }
        warp_mma(acc, sm, wm, wn, lane);
        __syncthreads();
    }

    const int g = lane >> 2, tg = lane & 3;
#pragma unroll
    for (int mt = 0; mt < 4; mt++)
#pragma unroll
        for (int nt = 0; nt < 4; nt++) {
            int r = r0 + wm * 64 + mt * 16 + g;
            int cl = wn * 32 + nt * 8 + tg * 2;
            float b0 = sBias[cl], b1 = sBias[cl + 1];
            float* p0 = out + (size_t)r * D_ + d0 + cl;
            *(float2*)p0 = make_float2(tanhf(acc[mt][nt][0] + b0), tanhf(acc[mt][nt][1] + b1));
            float* p1 = out + (size_t)(r + 8) * D_ + d0 + cl;
            *(float2*)p1 = make_float2(tanhf(acc[mt][nt][2] + b0), tanhf(acc[mt][nt][3] + b1));
        }
}

// ---------------------------------------------------------------- launch
extern "C" void kernel_launch(void* const* d_in, const int* in_sizes, int n_in,
                              void* d_out, int out_size) {
    const float* out_t = (const float*)d_in[0];  // [T,B,D]
    const float* ctx   = (const float*)d_in[1];  // [S,B,D]
    const float* W     = (const float*)d_in[2];  // [D,2D]
    const float* bias  = (const float*)d_in[3];  // [D]
    float* out = (float*)d_out;                  // [B,T,D]

    const int nconv = (int)(((size_t)T_ * B_ * D_ / 4) / 256);  // 32768 blocks
    k_split_qc<<<nconv, 256>>>(out_t, 0);
    k_split_qc<<<nconv, 256>>>(ctx,   1);
    k_split_cT<<<dim3(S_ / 32, D_ / 32, B_), dim3(32, 8)>>>(ctx);
    k_split_W<<<(int)(((size_t)D_ * K2_ / 4) / 256), 256>>>(W);

    g1_scores<<<dim3(S_ / BN, T_ / BM, B_), 256>>>();
    k_stats<<<(B_ * T_) / 8, 256>>>();
    g2_mix<<<dim3(D_ / BN, T_ / BM, B_), 256>>>();
    g3_out<<<dim3(D_ / BN, (B_ * T_) / BM), 256>>>(bias, out);
}

// round 11
// speedup vs baseline: 1.9904x; 1.1583x over previous
#include <cuda_runtime.h>
#include <cuda_fp16.h>
#include <cstdint>
#include <math.h>

// ---------------------------------------------------------------- problem dims
constexpr int T_ = 2048, S_ = 2048, B_ = 16, D_ = 1024;
constexpr int K2_ = 2 * D_;

// ---------------------------------------------------------------- tiling
constexpr int BM = 128, BN = 128, BK = 32;
constexpr int ROWH = 40;               // halves per smem row (pad: 32 data + 8)
constexpr int RB = ROWH * 2;           // 80 bytes per row
constexpr int REG = BM * RB;           // 10240 B per operand region
constexpr int OFF_AH = 0, OFF_AL = REG, OFF_BH = 2 * REG, OFF_BL = 3 * REG;
constexpr int SM_BYTES = 4 * REG;      // 40960 B (static shared, no opt-in needed)

constexpr float PSCALE = 4096.0f;      // keep softmax-P "lo" split out of fp16 denormals
constexpr float INVP = 1.0f / 4096.0f;

// ---------------------------------------------------------------- scratch (__device__ globals)
__device__ float g_scores[(size_t)B_ * T_ * S_];        // 256 MB
__device__ __half g_p_hi[(size_t)B_ * T_ * S_];         // softmax P (scaled by PSCALE), hi
__device__ __half g_p_lo[(size_t)B_ * T_ * S_];         // lo residual
__device__ __half g_q_hi[(size_t)B_ * T_ * D_];         // [B][T][D]
__device__ __half g_q_lo[(size_t)B_ * T_ * D_];
__device__ __half g_c_hi[(size_t)B_ * S_ * D_];         // [B][S][D]
__device__ __half g_c_lo[(size_t)B_ * S_ * D_];
__device__ __half g_cT_hi[(size_t)B_ * D_ * S_];        // [B][D][S]
__device__ __half g_cT_lo[(size_t)B_ * D_ * S_];
__device__ __half g_mix_hi[(size_t)B_ * T_ * D_];       // [B][T][D]
__device__ __half g_mix_lo[(size_t)B_ * T_ * D_];
__device__ __half g_W_hi[(size_t)D_ * K2_];             // [D][2D]
__device__ __half g_W_lo[(size_t)D_ * K2_];

// ---------------------------------------------------------------- helpers
// NOTE: no `volatile` — pure computation; let ptxas schedule freely.
__device__ __forceinline__ void mma4(float* c, const uint32_t* a, const uint32_t* b) {
    asm("mma.sync.aligned.m16n8k16.row.col.f32.f16.f16.f32 "
        "{%0,%1,%2,%3}, {%4,%5,%6,%7}, {%8,%9}, {%0,%1,%2,%3};"
        : "+f"(c[0]), "+f"(c[1]), "+f"(c[2]), "+f"(c[3])
        : "r"(a[0]), "r"(a[1]), "r"(a[2]), "r"(a[3]), "r"(b[0]), "r"(b[1]));
}
__device__ __forceinline__ void split2(float x, unsigned short& h, unsigned short& l) {
    __half hb = __float2half_rn(x);
    __half lb = __float2half_rn(x - __half2float(hb));
    h = __half_as_ushort(hb);
    l = __half_as_ushort(lb);
}

// Prefetch one 128x32-half region: 512 chunks of 16B, 2 per thread.
__device__ __forceinline__ void pref_region(uint4 (&r)[2], const __half* __restrict__ src,
                                            int ldk, int tid) {
#pragma unroll
    for (int j = 0; j < 2; j++) {
        int id = tid + j * 256;
        int row = id >> 2, c = id & 3;
        r[j] = *(const uint4*)(src + (size_t)row * ldk + c * 8);
    }
}
__device__ __forceinline__ void store_region(char* dst, const uint4 (&r)[2], int tid) {
#pragma unroll
    for (int j = 0; j < 2; j++) {
        int id = tid + j * 256;
        int row = id >> 2, c = id & 3;
        *(uint4*)(dst + row * RB + c * 16) = r[j];
    }
}

// Warp compute over one BK=32 tile: acc += Ah*Bh + Ah*Bl + Al*Bh.
// Term-major issue order: consecutive MMAs always hit DIFFERENT accumulators,
// so there are no back-to-back accumulator RAW chains (the R10 structure issued
// 3 dependent MMAs in a row into the same acc, paying full HMMA latency).
__device__ __forceinline__ void warp_mma(float (&acc)[4][4][4], const char* sm,
                                         int wm, int wn, int lane) {
    const int g = lane >> 2, tg = lane & 3;
#pragma unroll
    for (int ks = 0; ks < 2; ks++) {
        uint32_t ah[4][4], al[4][4];
#pragma unroll
        for (int mt = 0; mt < 4; mt++) {
            const int base = (wm * 64 + mt * 16 + g) * RB + (ks * 8 + tg) * 4;
            ah[mt][0] = *(const uint32_t*)(sm + OFF_AH + base);
            ah[mt][1] = *(const uint32_t*)(sm + OFF_AH + base + 8 * RB);
            ah[mt][2] = *(const uint32_t*)(sm + OFF_AH + base + 16);
            ah[mt][3] = *(const uint32_t*)(sm + OFF_AH + base + 8 * RB + 16);
            al[mt][0] = *(const uint32_t*)(sm + OFF_AL + base);
            al[mt][1] = *(const uint32_t*)(sm + OFF_AL + base + 8 * RB);
            al[mt][2] = *(const uint32_t*)(sm + OFF_AL + base + 16);
            al[mt][3] = *(const uint32_t*)(sm + OFF_AL + base + 8 * RB + 16);
        }
        uint32_t bh[4][2], bl[4][2];
#pragma unroll
        for (int nt = 0; nt < 4; nt++) {
            const int base = (wn * 32 + nt * 8 + g) * RB + (ks * 8 + tg) * 4;
            bh[nt][0] = *(const uint32_t*)(sm + OFF_BH + base);
            bh[nt][1] = *(const uint32_t*)(sm + OFF_BH + base + 16);
            bl[nt][0] = *(const uint32_t*)(sm + OFF_BL + base);
            bl[nt][1] = *(const uint32_t*)(sm + OFF_BL + base + 16);
        }
        // term 1: Ah * Bh
#pragma unroll
        for (int mt = 0; mt < 4; mt++)
#pragma unroll
            for (int nt = 0; nt < 4; nt++) mma4(acc[mt][nt], ah[mt], bh[nt]);
        // term 2: Ah * Bl
#pragma unroll
        for (int mt = 0; mt < 4; mt++)
#pragma unroll
            for (int nt = 0; nt < 4; nt++) mma4(acc[mt][nt], ah[mt], bl[nt]);
        // term 3: Al * Bh
#pragma unroll
        for (int mt = 0; mt < 4; mt++)
#pragma unroll
            for (int nt = 0; nt < 4; nt++) mma4(acc[mt][nt], al[mt], bh[nt]);
    }
}

// ---------------------------------------------------------------- conversion kernels
// which == 0 -> write g_q_hi/lo, which == 1 -> write g_c_hi/lo.
// Destination __device__ arrays referenced from DEVICE code (host-side symbol
// reference was the R8/R9 bug).
__global__ __launch_bounds__(256) void k_split_qc(const float* __restrict__ src, int which) {
    __half* __restrict__ hi = which ? g_c_hi : g_q_hi;
    __half* __restrict__ lo = which ? g_c_lo : g_q_lo;
    size_t e = ((size_t)blockIdx.x * 256 + threadIdx.x) * 4;
    int t = (int)(e / (B_ * D_));
    int rem = (int)(e % (B_ * D_));
    int b = rem / D_, d = rem % D_;
    float4 v = *(const float4*)(src + e);
    unsigned short h[4], l[4];
    split2(v.x, h[0], l[0]); split2(v.y, h[1], l[1]);
    split2(v.z, h[2], l[2]); split2(v.w, h[3], l[3]);
    size_t o = ((size_t)b * T_ + t) * D_ + d;
    *(uint2*)(hi + o) = make_uint2((uint32_t)h[0] | ((uint32_t)h[1] << 16),
                                   (uint32_t)h[2] | ((uint32_t)h[3] << 16));
    *(uint2*)(lo + o) = make_uint2((uint32_t)l[0] | ((uint32_t)l[1] << 16),
                                   (uint32_t)l[2] | ((uint32_t)l[3] << 16));
}

__global__ __launch_bounds__(256) void k_split_cT(const float* __restrict__ c) {
    __shared__ float tile[32][33];
    int b = blockIdx.z, d0 = blockIdx.y * 32, s0 = blockIdx.x * 32;
    int tx = threadIdx.x, ty = threadIdx.y;
    for (int r = ty; r < 32; r += 8)
        tile[r][tx] = c[((size_t)(s0 + r) * B_ + b) * D_ + d0 + tx];
    __syncthreads();
    for (int r = ty; r < 32; r += 8) {
        unsigned short h, l;
        split2(tile[tx][r], h, l);
        size_t o = ((size_t)b * D_ + d0 + r) * S_ + s0 + tx;
        g_cT_hi[o] = __ushort_as_half(h);
        g_cT_lo[o] = __ushort_as_half(l);
    }
}

__global__ __launch_bounds__(256) void k_split_W(const float* __restrict__ W) {
    size_t e = ((size_t)blockIdx.x * 256 + threadIdx.x) * 4;
    float4 v = *(const float4*)(W + e);
    unsigned short h[4], l[4];
    split2(v.x, h[0], l[0]); split2(v.y, h[1], l[1]);
    split2(v.z, h[2], l[2]); split2(v.w, h[3], l[3]);
    *(uint2*)(g_W_hi + e) = make_uint2((uint32_t)h[0] | ((uint32_t)h[1] << 16),
                                       (uint32_t)h[2] | ((uint32_t)h[3] << 16));
    *(uint2*)(g_W_lo + e) = make_uint2((uint32_t)l[0] | ((uint32_t)l[1] << 16),
                                       (uint32_t)l[2] | ((uint32_t)l[3] << 16));
}

// ---------------------------------------------------------------- G1: scores = q @ c^T
__global__ __launch_bounds__(256) void g1_scores() {
    __shared__ __align__(16) char sm[SM_BYTES];
    const int tid = threadIdx.x, lane = tid & 31, wid = tid >> 5;
    const int wm = wid >> 2, wn = wid & 3;
    const int b = blockIdx.z, t0 = blockIdx.y * BM, s0 = blockIdx.x * BN;

    const __half* Ah = g_q_hi + ((size_t)b * T_ + t0) * D_;
    const __half* Al = g_q_lo + ((size_t)b * T_ + t0) * D_;
    const __half* Bh = g_c_hi + ((size_t)b * S_ + s0) * D_;
    const __half* Bl = g_c_lo + ((size_t)b * S_ + s0) * D_;

    float acc[4][4][4];
#pragma unroll
    for (int i = 0; i < 4; i++)
#pragma unroll
        for (int j = 0; j < 4; j++)
#pragma unroll
            for (int k = 0; k < 4; k++) acc[i][j][k] = 0.f;

    uint4 rah[2], ral[2], rbh[2], rbl[2];
    const int NI = D_ / BK;  // 32
    pref_region(rah, Ah, D_, tid);
    pref_region(ral, Al, D_, tid);
    pref_region(rbh, Bh, D_, tid);
    pref_region(rbl, Bl, D_, tid);
    for (int i = 0; i < NI; i++) {
        store_region(sm + OFF_AH, rah, tid);
        store_region(sm + OFF_AL, ral, tid);
        store_region(sm + OFF_BH, rbh, tid);
        store_region(sm + OFF_BL, rbl, tid);
        __syncthreads();
        if (i + 1 < NI) {
            int k0 = (i + 1) * BK;
            pref_region(rah, Ah + k0, D_, tid);
            pref_region(ral, Al + k0, D_, tid);
            pref_region(rbh, Bh + k0, D_, tid);
            pref_region(rbl, Bl + k0, D_, tid);
        }
        warp_mma(acc, sm, wm, wn, lane);
        __syncthreads();
    }

    const int g = lane >> 2, tg = lane & 3;
#pragma unroll
    for (int mt = 0; mt < 4; mt++)
#pragma unroll
        for (int nt = 0; nt < 4; nt++) {
            int r = t0 + wm * 64 + mt * 16 + g;
            int cix = s0 + wn * 32 + nt * 8 + tg * 2;
            float* p0 = g_scores + ((size_t)b * T_ + r) * S_ + cix;
            *(float2*)p0 = make_float2(acc[mt][nt][0], acc[mt][nt][1]);
            float* p1 = g_scores + ((size_t)b * T_ + r + 8) * S_ + cix;
            *(float2*)p1 = make_float2(acc[mt][nt][2], acc[mt][nt][3]);
        }
}

// ---------------------------------------------------------------- K2: row stats + P conversion (fused)
// Pass 1: online max/sum with the ==0 mask.  Pass 2 (row L2-hot): write
// P = exp(x-m)/sum * PSCALE as fp16 hi/lo into g_p_hi / g_p_lo.
__global__ __launch_bounds__(256) void k_stats() {
    const int row = blockIdx.x * 8 + (threadIdx.x >> 5);
    const int lane = threadIdx.x & 31;
    const float* p = g_scores + (size_t)row * S_;
    float m = -INFINITY, sum = 0.f;
    for (int s = lane * 4; s < S_; s += 128) {
        float4 v = *(const float4*)(p + s);
        float vals[4] = {v.x, v.y, v.z, v.w};
#pragma unroll
        for (int i = 0; i < 4; i++) {
            float val = vals[i];
            if (val != 0.0f) {
                if (val > m) { sum = sum * __expf(m - val) + 1.0f; m = val; }
                else         { sum += __expf(val - m); }
            }
        }
    }
#pragma unroll
    for (int off = 16; off; off >>= 1) {
        float mo = __shfl_xor_sync(0xffffffffu, m, off);
        float so = __shfl_xor_sync(0xffffffffu, sum, off);
        float mn = fmaxf(m, mo);
        sum = sum * __expf(m - mn) + so * __expf(mo - mn);
        m = mn;
    }
    // after butterfly, every lane holds the final (m, sum)
    const float scale = PSCALE / sum;
    __half* ph = g_p_hi + (size_t)row * S_;
    __half* pl = g_p_lo + (size_t)row * S_;
    for (int s = lane * 4; s < S_; s += 128) {
        float4 v = *(const float4*)(p + s);
        float vals[4] = {v.x, v.y, v.z, v.w};
        unsigned short h[4], l[4];
#pragma unroll
        for (int i = 0; i < 4; i++) {
            float pv = (vals[i] == 0.0f) ? 0.0f : __expf(vals[i] - m) * scale;
            split2(pv, h[i], l[i]);
        }
        *(uint2*)(ph + s) = make_uint2((uint32_t)h[0] | ((uint32_t)h[1] << 16),
                                       (uint32_t)h[2] | ((uint32_t)h[3] << 16));
        *(uint2*)(pl + s) = make_uint2((uint32_t)l[0] | ((uint32_t)l[1] << 16),
                                       (uint32_t)l[2] | ((uint32_t)l[3] << 16));
    }
}

// ---------------------------------------------------------------- G2: mix = P @ c  (pure GEMM now)
__global__ __launch_bounds__(256) void g2_mix() {
    __shared__ __align__(16) char sm[SM_BYTES];
    const int tid = threadIdx.x, lane = tid & 31, wid = tid >> 5;
    const int wm = wid >> 2, wn = wid & 3;
    const int b = blockIdx.z, t0 = blockIdx.y * BM, d0 = blockIdx.x * BN;

    const __half* Ah = g_p_hi + ((size_t)b * T_ + t0) * S_;
    const __half* Al = g_p_lo + ((size_t)b * T_ + t0) * S_;
    const __half* Bh = g_cT_hi + ((size_t)b * D_ + d0) * S_;
    const __half* Bl = g_cT_lo + ((size_t)b * D_ + d0) * S_;

    float acc[4][4][4];
#pragma unroll
    for (int i = 0; i < 4; i++)
#pragma unroll
        for (int j = 0; j < 4; j++)
#pragma unroll
            for (int k = 0; k < 4; k++) acc[i][j][k] = 0.f;

    uint4 rah[2], ral[2], rbh[2], rbl[2];
    const int NI = S_ / BK;  // 64
    pref_region(rah, Ah, S_, tid);
    pref_region(ral, Al, S_, tid);
    pref_region(rbh, Bh, S_, tid);
    pref_region(rbl, Bl, S_, tid);
    for (int i = 0; i < NI; i++) {
        store_region(sm + OFF_AH, rah, tid);
        store_region(sm + OFF_AL, ral, tid);
        store_region(sm + OFF_BH, rbh, tid);
        store_region(sm + OFF_BL, rbl, tid);
        __syncthreads();
        if (i + 1 < NI) {
            int k0 = (i + 1) * BK;
            pref_region(rah, Ah + k0, S_, tid);
            pref_region(ral, Al + k0, S_, tid);
            pref_region(rbh, Bh + k0, S_, tid);
            pref_region(rbl, Bl + k0, S_, tid);
        }
        warp_mma(acc, sm, wm, wn, lane);
        __syncthreads();
    }

    const int g = lane >> 2, tg = lane & 3;
#pragma unroll
    for (int mt = 0; mt < 4; mt++)
#pragma unroll
        for (int nt = 0; nt < 4; nt++) {
            int r = t0 + wm * 64 + mt * 16 + g;
            int cix = d0 + wn * 32 + nt * 8 + tg * 2;
#pragma unroll
            for (int hrow = 0; hrow < 2; hrow++) {
                size_t o = ((size_t)b * T_ + r + hrow * 8) * D_ + cix;
                unsigned short h0, l0, h1, l1;
                split2(acc[mt][nt][2 * hrow] * INVP,     h0, l0);
                split2(acc[mt][nt][2 * hrow + 1] * INVP, h1, l1);
                *(uint32_t*)(g_mix_hi + o) = (uint32_t)h0 | ((uint32_t)h1 << 16);
                *(uint32_t*)(g_mix_lo + o) = (uint32_t)l0 | ((uint32_t)l1 << 16);
            }
        }
}

// ---------------------------------------------------------------- G3: out = tanh([mix,q] @ W^T + b)
__global__ __launch_bounds__(256) void g3_out(const float* __restrict__ bias,
                                              float* __restrict__ out) {
    __shared__ __align__(16) char sm[SM_BYTES];
    __shared__ float sBias[BN];
    const int tid = threadIdx.x, lane = tid & 31, wid = tid >> 5;
    const int wm = wid >> 2, wn = wid & 3;
    const int r0 = blockIdx.y * BM, d0 = blockIdx.x * BN;
    if (tid < BN) sBias[tid] = bias[d0 + tid];
    __syncthreads();

    const __half* Wh = g_W_hi + (size_t)d0 * K2_;
    const __half* Wl = g_W_lo + (size_t)d0 * K2_;

    float acc[4][4][4];
#pragma unroll
    for (int i = 0; i < 4; i++)
#pragma unroll
        for (int j = 0; j < 4; j++)
#pragma unroll
            for (int k = 0; k < 4; k++) acc[i][j][k] = 0.f;

    uint4 rah[2], ral[2], rbh[2], rbl[2];
    const int NI = K2_ / BK;  // 64
    auto prefA = [&](int k0) {
        const __half* Ah = (k0 < D_) ? g_mix_hi + (size_t)r0 * D_ + k0
                                     : g_q_hi  + (size_t)r0 * D_ + (k0 - D_);
        const __half* Al = (k0 < D_) ? g_mix_lo + (size_t)r0 * D_ + k0
                                     : g_q_lo  + (size_t)r0 * D_ + (k0 - D_);
        pref_region(rah, Ah, D_, tid);
        pref_region(ral, Al, D_, tid);
    };
    prefA(0);
    pref_region(rbh, Wh, K2_, tid);
    pref_region(rbl, Wl, K2_, tid);
    for (int i = 0; i < NI; i++) {
        store_region(sm + OFF_AH, rah, tid);
        store_region(sm + OFF_AL, ral, tid);
        store_region(sm + OFF_BH, rbh, tid);
        store_region(sm + OFF_BL, rbl, tid);
        __syncthreads();
        if (i + 1 < NI) {
            int k0 = (i + 1) * BK;
            prefA(k0);
            pref_region(rbh, Wh + k0, K2_, tid);
            pref_region(rbl, Wl + k0, K2_, tid);
        }
        warp_mma(acc, sm, wm, wn, lane);
        __syncthreads();
    }

    const int g = lane >> 2, tg = lane & 3;
#pragma unroll
    for (int mt = 0; mt < 4; mt++)
#pragma unroll
        for (int nt = 0; nt < 4; nt++) {
            int r = r0 + wm * 64 + mt * 16 + g;
            int cl = wn * 32 + nt * 8 + tg * 2;
            float b0 = sBias[cl], b1 = sBias[cl + 1];
            float* p0 = out + (size_t)r * D_ + d0 + cl;
            *(float2*)p0 = make_float2(tanhf(acc[mt][nt][0] + b0), tanhf(acc[mt][nt][1] + b1));
            float* p1 = out + (size_t)(r + 8) * D_ + d0 + cl;
            *(float2*)p1 = make_float2(tanhf(acc[mt][nt][2] + b0), tanhf(acc[mt][nt][3] + b1));
        }
}

// ---------------------------------------------------------------- launch
extern "C" void kernel_launch(void* const* d_in, const int* in_sizes, int n_in,
                              void* d_out, int out_size) {
    const float* out_t = (const float*)d_in[0];  // [T,B,D]
    const float* ctx   = (const float*)d_in[1];  // [S,B,D]
    const float* W     = (const float*)d_in[2];  // [D,2D]
    const float* bias  = (const float*)d_in[3];  // [D]
    float* out = (float*)d_out;                  // [B,T,D]

    const int nconv = (int)(((size_t)T_ * B_ * D_ / 4) / 256);  // 32768 blocks
    k_split_qc<<<nconv, 256>>>(out_t, 0);
    k_split_qc<<<nconv, 256>>>(ctx,   1);
    k_split_cT<<<dim3(S_ / 32, D_ / 32, B_), dim3(32, 8)>>>(ctx);
    k_split_W<<<(int)(((size_t)D_ * K2_ / 4) / 256), 256>>>(W);

    g1_scores<<<dim3(S_ / BN, T_ / BM, B_), 256>>>();
    k_stats<<<(B_ * T_) / 8, 256>>>();
    g2_mix<<<dim3(D_ / BN, T_ / BM, B_), 256>>>();
    g3_out<<<dim3(D_ / BN, (B_ * T_) / BM), 256>>>(bias, out);
}

// round 13
// speedup vs baseline: 2.2463x; 1.1286x over previous
#include <cuda_runtime.h>
#include <cuda_fp16.h>
#include <cstdint>
#include <math.h>

// ---------------------------------------------------------------- problem dims
constexpr int T_ = 2048, S_ = 2048, B_ = 16, D_ = 1024;
constexpr int K2_ = 2 * D_;

// ---------------------------------------------------------------- tiling
constexpr int BM = 128, BN = 128, BK = 32;
constexpr int ROWH = 40;               // halves per smem row (pad: 32 data + 8)
constexpr int RB = ROWH * 2;           // 80 bytes per row
constexpr int REG = BM * RB;           // 10240 B per operand region
constexpr int OFF_AH = 0, OFF_AL = REG, OFF_BH = 2 * REG, OFF_BL = 3 * REG;
constexpr int SM_BYTES = 4 * REG;      // 40960 B (static shared, no opt-in needed)

constexpr float PSCALE = 4096.0f;      // keep softmax-P "lo" split out of fp16 denormals
constexpr float INVP = 1.0f / 4096.0f;

// ---------------------------------------------------------------- scratch (__device__ globals)
__device__ float g_scores[(size_t)B_ * T_ * S_];        // 256 MB
__device__ __half g_p_hi[(size_t)B_ * T_ * S_];         // softmax P (scaled by PSCALE), hi
__device__ __half g_p_lo[(size_t)B_ * T_ * S_];         // lo residual
__device__ __half g_q_hi[(size_t)B_ * T_ * D_];         // [B][T][D]
__device__ __half g_q_lo[(size_t)B_ * T_ * D_];
__device__ __half g_c_hi[(size_t)B_ * S_ * D_];         // [B][S][D]
__device__ __half g_c_lo[(size_t)B_ * S_ * D_];
__device__ __half g_cT_hi[(size_t)B_ * D_ * S_];        // [B][D][S]
__device__ __half g_cT_lo[(size_t)B_ * D_ * S_];
__device__ __half g_mix_hi[(size_t)B_ * T_ * D_];       // [B][T][D]
__device__ __half g_mix_lo[(size_t)B_ * T_ * D_];
__device__ __half g_W_hi[(size_t)D_ * K2_];             // [D][2D]
__device__ __half g_W_lo[(size_t)D_ * K2_];

// ---------------------------------------------------------------- helpers
__device__ __forceinline__ uint32_t s2u(const void* p) {
    uint32_t a;
    asm("{ .reg .u64 t; cvta.to.shared.u64 t, %1; cvt.u32.u64 %0, t; }" : "=r"(a) : "l"(p));
    return a;
}
// pure computation; no volatile, let ptxas schedule
__device__ __forceinline__ void mma4(float* c, const uint32_t* a, const uint32_t* b) {
    asm("mma.sync.aligned.m16n8k16.row.col.f32.f16.f16.f32 "
        "{%0,%1,%2,%3}, {%4,%5,%6,%7}, {%8,%9}, {%0,%1,%2,%3};"
        : "+f"(c[0]), "+f"(c[1]), "+f"(c[2]), "+f"(c[3])
        : "r"(a[0]), "r"(a[1]), "r"(a[2]), "r"(a[3]), "r"(b[0]), "r"(b[1]));
}
__device__ __forceinline__ void ldsm_x4(uint32_t* r, uint32_t addr) {
    asm volatile("ldmatrix.sync.aligned.m8n8.x4.shared.b16 {%0,%1,%2,%3}, [%4];"
                 : "=r"(r[0]), "=r"(r[1]), "=r"(r[2]), "=r"(r[3]) : "r"(addr));
}
__device__ __forceinline__ void split2(float x, unsigned short& h, unsigned short& l) {
    __half hb = __float2half_rn(x);
    __half lb = __float2half_rn(x - __half2float(hb));
    h = __half_as_ushort(hb);
    l = __half_as_ushort(lb);
}

// Prefetch one 128x32-half region: 512 chunks of 16B, 2 per thread.
__device__ __forceinline__ void pref_region(uint4 (&r)[2], const __half* __restrict__ src,
                                            int ldk, int tid) {
#pragma unroll
    for (int j = 0; j < 2; j++) {
        int id = tid + j * 256;
        int row = id >> 2, c = id & 3;
        r[j] = *(const uint4*)(src + (size_t)row * ldk + c * 8);
    }
}
__device__ __forceinline__ void store_region(char* dst, const uint4 (&r)[2], int tid) {
#pragma unroll
    for (int j = 0; j < 2; j++) {
        int id = tid + j * 256;
        int row = id >> 2, c = id & 3;
        *(uint4*)(dst + row * RB + c * 16) = r[j];
    }
}

// Warp compute over one BK=32 tile: acc += Ah*Bh + Ah*Bl + Al*Bh.
// Fragments via ldmatrix.x4 (24 LDSM/tile vs 96 LDS.32 in the R11 version).
//
// A x4 matrices for tile-row mt: {m0..7,k0..7},{m8..15,k0..7},{m0..7,k8..15},{m8..15,k8..15}
//   -> regs r0..r3 == a0..a3 of mma.m16n8k16.  Lane i=lane>>3, j=lane&7:
//      off = ((i&1)*8 + j)*RB + (i>>1)*16
// B x4 matrices for nt pair p: {n(2p),k0..7},{n(2p),k8..15},{n(2p+1),k0..7},{n(2p+1),k8..15}
//   -> regs r0,r1 = b[2p][0..1], r2,r3 = b[2p+1][0..1].  Lane off:
//      off = ((i>>1)*8 + j)*RB + (i&1)*16
// Rows are RB=80B apart -> banks 20j mod 32 all distinct -> conflict-free.
__device__ __forceinline__ void warp_mma(float (&acc)[4][4][4], uint32_t sb,
                                         int wm, int wn, int lane) {
    const uint32_t i83 = (uint32_t)(lane >> 3), j = (uint32_t)(lane & 7);
    const uint32_t aoffL = ((i83 & 1) * 8 + j) * RB + (i83 >> 1) * 16;
    const uint32_t boffL = ((i83 >> 1) * 8 + j) * RB + (i83 & 1) * 16;
    const uint32_t abase = sb + (uint32_t)(wm * 64) * RB + aoffL;
    const uint32_t bbase = sb + (uint32_t)(wn * 32) * RB + boffL;
#pragma unroll
    for (int ks = 0; ks < 2; ks++) {
        uint32_t ah[4][4], al[4][4], bh[4][2], bl[4][2];
#pragma unroll
        for (int mt = 0; mt < 4; mt++) {
            const uint32_t o = abase + (uint32_t)(mt * 16) * RB + ks * 32;
            ldsm_x4(ah[mt], OFF_AH + o);
            ldsm_x4(al[mt], OFF_AL + o);
        }
#pragma unroll
        for (int p = 0; p < 2; p++) {
            const uint32_t o = bbase + (uint32_t)(p * 16) * RB + ks * 32;
            uint32_t th[4], tl[4];
            ldsm_x4(th, OFF_BH + o);
            ldsm_x4(tl, OFF_BL + o);
            bh[2 * p][0] = th[0]; bh[2 * p][1] = th[1];
            bh[2 * p + 1][0] = th[2]; bh[2 * p + 1][1] = th[3];
            bl[2 * p][0] = tl[0]; bl[2 * p][1] = tl[1];
            bl[2 * p + 1][0] = tl[2]; bl[2 * p + 1][1] = tl[3];
        }
        // term-major order: consecutive MMAs hit different accumulators
#pragma unroll
        for (int mt = 0; mt < 4; mt++)
#pragma unroll
            for (int nt = 0; nt < 4; nt++) mma4(acc[mt][nt], ah[mt], bh[nt]);
#pragma unroll
        for (int mt = 0; mt < 4; mt++)
#pragma unroll
            for (int nt = 0; nt < 4; nt++) mma4(acc[mt][nt], ah[mt], bl[nt]);
#pragma unroll
        for (int mt = 0; mt < 4; mt++)
#pragma unroll
            for (int nt = 0; nt < 4; nt++) mma4(acc[mt][nt], al[mt], bh[nt]);
    }
}

// ---------------------------------------------------------------- conversion kernels
// which == 0 -> write g_q_hi/lo, which == 1 -> write g_c_hi/lo.
// Destination __device__ arrays referenced from DEVICE code (host-side symbol
// reference was the R8/R9 bug).
__global__ __launch_bounds__(256) void k_split_qc(const float* __restrict__ src, int which) {
    __half* __restrict__ hi = which ? g_c_hi : g_q_hi;
    __half* __restrict__ lo = which ? g_c_lo : g_q_lo;
    size_t e = ((size_t)blockIdx.x * 256 + threadIdx.x) * 4;
    int t = (int)(e / (B_ * D_));
    int rem = (int)(e % (B_ * D_));
    int b = rem / D_, d = rem % D_;
    float4 v = *(const float4*)(src + e);
    unsigned short h[4], l[4];
    split2(v.x, h[0], l[0]); split2(v.y, h[1], l[1]);
    split2(v.z, h[2], l[2]); split2(v.w, h[3], l[3]);
    size_t o = ((size_t)b * T_ + t) * D_ + d;
    *(uint2*)(hi + o) = make_uint2((uint32_t)h[0] | ((uint32_t)h[1] << 16),
                                   (uint32_t)h[2] | ((uint32_t)h[3] << 16));
    *(uint2*)(lo + o) = make_uint2((uint32_t)l[0] | ((uint32_t)l[1] << 16),
                                   (uint32_t)l[2] | ((uint32_t)l[3] << 16));
}

__global__ __launch_bounds__(256) void k_split_cT(const float* __restrict__ c) {
    __shared__ float tile[32][33];
    int b = blockIdx.z, d0 = blockIdx.y * 32, s0 = blockIdx.x * 32;
    int tx = threadIdx.x, ty = threadIdx.y;
    for (int r = ty; r < 32; r += 8)
        tile[r][tx] = c[((size_t)(s0 + r) * B_ + b) * D_ + d0 + tx];
    __syncthreads();
    for (int r = ty; r < 32; r += 8) {
        unsigned short h, l;
        split2(tile[tx][r], h, l);
        size_t o = ((size_t)b * D_ + d0 + r) * S_ + s0 + tx;
        g_cT_hi[o] = __ushort_as_half(h);
        g_cT_lo[o] = __ushort_as_half(l);
    }
}

__global__ __launch_bounds__(256) void k_split_W(const float* __restrict__ W) {
    size_t e = ((size_t)blockIdx.x * 256 + threadIdx.x) * 4;
    float4 v = *(const float4*)(W + e);
    unsigned short h[4], l[4];
    split2(v.x, h[0], l[0]); split2(v.y, h[1], l[1]);
    split2(v.z, h[2], l[2]); split2(v.w, h[3], l[3]);
    *(uint2*)(g_W_hi + e) = make_uint2((uint32_t)h[0] | ((uint32_t)h[1] << 16),
                                       (uint32_t)h[2] | ((uint32_t)h[3] << 16));
    *(uint2*)(g_W_lo + e) = make_uint2((uint32_t)l[0] | ((uint32_t)l[1] << 16),
                                       (uint32_t)l[2] | ((uint32_t)l[3] << 16));
}

// ---------------------------------------------------------------- G1: scores = q @ c^T
__global__ __launch_bounds__(256) void g1_scores() {
    __shared__ __align__(16) char sm[SM_BYTES];
    const int tid = threadIdx.x, lane = tid & 31, wid = tid >> 5;
    const int wm = wid >> 2, wn = wid & 3;
    const int b = blockIdx.z, t0 = blockIdx.y * BM, s0 = blockIdx.x * BN;
    const uint32_t sb = s2u(sm);

    const __half* Ah = g_q_hi + ((size_t)b * T_ + t0) * D_;
    const __half* Al = g_q_lo + ((size_t)b * T_ + t0) * D_;
    const __half* Bh = g_c_hi + ((size_t)b * S_ + s0) * D_;
    const __half* Bl = g_c_lo + ((size_t)b * S_ + s0) * D_;

    float acc[4][4][4];
#pragma unroll
    for (int i = 0; i < 4; i++)
#pragma unroll
        for (int j = 0; j < 4; j++)
#pragma unroll
            for (int k = 0; k < 4; k++) acc[i][j][k] = 0.f;

    uint4 rah[2], ral[2], rbh[2], rbl[2];
    const int NI = D_ / BK;  // 32
    pref_region(rah, Ah, D_, tid);
    pref_region(ral, Al, D_, tid);
    pref_region(rbh, Bh, D_, tid);
    pref_region(rbl, Bl, D_, tid);
    for (int i = 0; i < NI; i++) {
        store_region(sm + OFF_AH, rah, tid);
        store_region(sm + OFF_AL, ral, tid);
        store_region(sm + OFF_BH, rbh, tid);
        store_region(sm + OFF_BL, rbl, tid);
        __syncthreads();
        if (i + 1 < NI) {
            int k0 = (i + 1) * BK;
            pref_region(rah, Ah + k0, D_, tid);
            pref_region(ral, Al + k0, D_, tid);
            pref_region(rbh, Bh + k0, D_, tid);
            pref_region(rbl, Bl + k0, D_, tid);
        }
        warp_mma(acc, sb, wm, wn, lane);
        __syncthreads();
    }

    const int g = lane >> 2, tg = lane & 3;
#pragma unroll
    for (int mt = 0; mt < 4; mt++)
#pragma unroll
        for (int nt = 0; nt < 4; nt++) {
            int r = t0 + wm * 64 + mt * 16 + g;
            int cix = s0 + wn * 32 + nt * 8 + tg * 2;
            float* p0 = g_scores + ((size_t)b * T_ + r) * S_ + cix;
            *(float2*)p0 = make_float2(acc[mt][nt][0], acc[mt][nt][1]);
            float* p1 = g_scores + ((size_t)b * T_ + r + 8) * S_ + cix;
            *(float2*)p1 = make_float2(acc[mt][nt][2], acc[mt][nt][3]);
        }
}

// ---------------------------------------------------------------- K2: row stats + P conversion (fused)
__global__ __launch_bounds__(256) void k_stats() {
    const int row = blockIdx.x * 8 + (threadIdx.x >> 5);
    const int lane = threadIdx.x & 31;
    const float* p = g_scores + (size_t)row * S_;
    float m = -INFINITY, sum = 0.f;
    for (int s = lane * 4; s < S_; s += 128) {
        float4 v = *(const float4*)(p + s);
        float vals[4] = {v.x, v.y, v.z, v.w};
#pragma unroll
        for (int i = 0; i < 4; i++) {
            float val = vals[i];
            if (val != 0.0f) {
                if (val > m) { sum = sum * __expf(m - val) + 1.0f; m = val; }
                else         { sum += __expf(val - m); }
            }
        }
    }
#pragma unroll
    for (int off = 16; off; off >>= 1) {
        float mo = __shfl_xor_sync(0xffffffffu, m, off);
        float so = __shfl_xor_sync(0xffffffffu, sum, off);
        float mn = fmaxf(m, mo);
        sum = sum * __expf(m - mn) + so * __expf(mo - mn);
        m = mn;
    }
    const float scale = PSCALE / sum;
    __half* ph = g_p_hi + (size_t)row * S_;
    __half* pl = g_p_lo + (size_t)row * S_;
    for (int s = lane * 4; s < S_; s += 128) {
        float4 v = *(const float4*)(p + s);
        float vals[4] = {v.x, v.y, v.z, v.w};
        unsigned short h[4], l[4];
#pragma unroll
        for (int i = 0; i < 4; i++) {
            float pv = (vals[i] == 0.0f) ? 0.0f : __expf(vals[i] - m) * scale;
            split2(pv, h[i], l[i]);
        }
        *(uint2*)(ph + s) = make_uint2((uint32_t)h[0] | ((uint32_t)h[1] << 16),
                                       (uint32_t)h[2] | ((uint32_t)h[3] << 16));
        *(uint2*)(pl + s) = make_uint2((uint32_t)l[0] | ((uint32_t)l[1] << 16),
                                       (uint32_t)l[2] | ((uint32_t)l[3] << 16));
    }
}

// ---------------------------------------------------------------- G2: mix = P @ c  (pure GEMM)
__global__ __launch_bounds__(256) void g2_mix() {
    __shared__ __align__(16) char sm[SM_BYTES];
    const int tid = threadIdx.x, lane = tid & 31, wid = tid >> 5;
    const int wm = wid >> 2, wn = wid & 3;
    const int b = blockIdx.z, t0 = blockIdx.y * BM, d0 = blockIdx.x * BN;
    const uint32_t sb = s2u(sm);

    const __half* Ah = g_p_hi + ((size_t)b * T_ + t0) * S_;
    const __half* Al = g_p_lo + ((size_t)b * T_ + t0) * S_;
    const __half* Bh = g_cT_hi + ((size_t)b * D_ + d0) * S_;
    const __half* Bl = g_cT_lo + ((size_t)b * D_ + d0) * S_;

    float acc[4][4][4];
#pragma unroll
    for (int i = 0; i < 4; i++)
#pragma unroll
        for (int j = 0; j < 4; j++)
#pragma unroll
            for (int k = 0; k < 4; k++) acc[i][j][k] = 0.f;

    uint4 rah[2], ral[2], rbh[2], rbl[2];
    const int NI = S_ / BK;  // 64
    pref_region(rah, Ah, S_, tid);
    pref_region(ral, Al, S_, tid);
    pref_region(rbh, Bh, S_, tid);
    pref_region(rbl, Bl, S_, tid);
    for (int i = 0; i < NI; i++) {
        store_region(sm + OFF_AH, rah, tid);
        store_region(sm + OFF_AL, ral, tid);
        store_region(sm + OFF_BH, rbh, tid);
        store_region(sm + OFF_BL, rbl, tid);
        __syncthreads();
        if (i + 1 < NI) {
            int k0 = (i + 1) * BK;
            pref_region(rah, Ah + k0, S_, tid);
            pref_region(ral, Al + k0, S_, tid);
            pref_region(rbh, Bh + k0, S_, tid);
            pref_region(rbl, Bl + k0, S_, tid);
        }
        warp_mma(acc, sb, wm, wn, lane);
        __syncthreads();
    }

    const int g = lane >> 2, tg = lane & 3;
#pragma unroll
    for (int mt = 0; mt < 4; mt++)
#pragma unroll
        for (int nt = 0; nt < 4; nt++) {
            int r = t0 + wm * 64 + mt * 16 + g;
            int cix = d0 + wn * 32 + nt * 8 + tg * 2;
#pragma unroll
            for (int hrow = 0; hrow < 2; hrow++) {
                size_t o = ((size_t)b * T_ + r + hrow * 8) * D_ + cix;
                unsigned short h0, l0, h1, l1;
                split2(acc[mt][nt][2 * hrow] * INVP,     h0, l0);
                split2(acc[mt][nt][2 * hrow + 1] * INVP, h1, l1);
                *(uint32_t*)(g_mix_hi + o) = (uint32_t)h0 | ((uint32_t)h1 << 16);
                *(uint32_t*)(g_mix_lo + o) = (uint32_t)l0 | ((uint32_t)l1 << 16);
            }
        }
}

// ---------------------------------------------------------------- G3: out = tanh([mix,q] @ W^T + b)
__global__ __launch_bounds__(256) void g3_out(const float* __restrict__ bias,
                                              float* __restrict__ out) {
    __shared__ __align__(16) char sm[SM_BYTES];
    __shared__ float sBias[BN];
    const int tid = threadIdx.x, lane = tid & 31, wid = tid >> 5;
    const int wm = wid >> 2, wn = wid & 3;
    const int r0 = blockIdx.y * BM, d0 = blockIdx.x * BN;
    const uint32_t sb = s2u(sm);
    if (tid < BN) sBias[tid] = bias[d0 + tid];
    __syncthreads();

    const __half* Wh = g_W_hi + (size_t)d0 * K2_;
    const __half* Wl = g_W_lo + (size_t)d0 * K2_;

    float acc[4][4][4];
#pragma unroll
    for (int i = 0; i < 4; i++)
#pragma unroll
        for (int j = 0; j < 4; j++)
#pragma unroll
            for (int k = 0; k < 4; k++) acc[i][j][k] = 0.f;

    uint4 rah[2], ral[2], rbh[2], rbl[2];
    const int NI = K2_ / BK;  // 64
    auto prefA = [&](int k0) {
        const __half* Ah = (k0 < D_) ? g_mix_hi + (size_t)r0 * D_ + k0
                                     : g_q_hi  + (size_t)r0 * D_ + (k0 - D_);
        const __half* Al = (k0 < D_) ? g_mix_lo + (size_t)r0 * D_ + k0
                                     : g_q_lo  + (size_t)r0 * D_ + (k0 - D_);
        pref_region(rah, Ah, D_, tid);
        pref_region(ral, Al, D_, tid);
    };
    prefA(0);
    pref_region(rbh, Wh, K2_, tid);
    pref_region(rbl, Wl, K2_, tid);
    for (int i = 0; i < NI; i++) {
        store_region(sm + OFF_AH, rah, tid);
        store_region(sm + OFF_AL, ral, tid);
        store_region(sm + OFF_BH, rbh, tid);
        store_region(sm + OFF_BL, rbl, tid);
        __syncthreads();
        if (i + 1 < NI) {
            int k0 = (i + 1) * BK;
            prefA(k0);
            pref_region(rbh, Wh + k0, K2_, tid);
            pref_region(rbl, Wl + k0, K2_, tid);
        }
        warp_mma(acc, sb, wm, wn, lane);
        __syncthreads();
    }

    const int g = lane >> 2, tg = lane & 3;
#pragma unroll
    for (int mt = 0; mt < 4; mt++)
#pragma unroll
        for (int nt = 0; nt < 4; nt++) {
            int r = r0 + wm * 64 + mt * 16 + g;
            int cl = wn * 32 + nt * 8 + tg * 2;
            float b0 = sBias[cl], b1 = sBias[cl + 1];
            float* p0 = out + (size_t)r * D_ + d0 + cl;
            *(float2*)p0 = make_float2(tanhf(acc[mt][nt][0] + b0), tanhf(acc[mt][nt][1] + b1));
            float* p1 = out + (size_t)(r + 8) * D_ + d0 + cl;
            *(float2*)p1 = make_float2(tanhf(acc[mt][nt][2] + b0), tanhf(acc[mt][nt][3] + b1));
        }
}

// ---------------------------------------------------------------- launch
extern "C" void kernel_launch(void* const* d_in, const int* in_sizes, int n_in,
                              void* d_out, int out_size) {
    const float* out_t = (const float*)d_in[0];  // [T,B,D]
    const float* ctx   = (const float*)d_in[1];  // [S,B,D]
    const float* W     = (const float*)d_in[2];  // [D,2D]
    const float* bias  = (const float*)d_in[3];  // [D]
    float* out = (float*)d_out;                  // [B,T,D]

    const int nconv = (int)(((size_t)T_ * B_ * D_ / 4) / 256);  // 32768 blocks
    k_split_qc<<<nconv, 256>>>(out_t, 0);
    k_split_qc<<<nconv, 256>>>(ctx,   1);
    k_split_cT<<<dim3(S_ / 32, D_ / 32, B_), dim3(32, 8)>>>(ctx);
    k_split_W<<<(int)(((size_t)D_ * K2_ / 4) / 256), 256>>>(W);

    g1_scores<<<dim3(S_ / BN, T_ / BM, B_), 256>>>();
    k_stats<<<(B_ * T_) / 8, 256>>>();
    g2_mix<<<dim3(D_ / BN, T_ / BM, B_), 256>>>();
    g3_out<<<dim3(D_ / BN, (B_ * T_) / BM), 256>>>(bias, out);
}